// round 2
// baseline (speedup 1.0000x reference)
#include <cuda_runtime.h>

// Problem constants
#define B_  2
#define L_  4096
#define D_  512
#define H_  8
#define DK_ 64
#define M_  (B_*L_)   // 8192 rows for the projection GEMMs

// Scratch (static device globals — allocation-free per harness rules)
__device__ __align__(16) float g_Q[(size_t)B_*H_*L_*DK_];
__device__ __align__(16) float g_K[(size_t)B_*H_*L_*DK_];
__device__ __align__(16) float g_V[(size_t)B_*H_*L_*DK_];
__device__ __align__(16) float g_O[(size_t)B_*L_*D_];

// ---------------------------------------------------------------------------
// Fused QKV projection: out = x @ W^T + b, scattered into [B,H,L,dk].
// Tiled SGEMM: BM=BN=64, BK=16, 256 threads, 4x4 micro-tile per thread.
// gridDim.z in {0,1,2} selects (Wq,bq,g_Q) / (Wk,bk,g_K) / (Wv,bv,g_V).
// ---------------------------------------------------------------------------
__global__ __launch_bounds__(256) void qkv_gemm(
    const float* __restrict__ x,
    const float* __restrict__ Wq, const float* __restrict__ bq,
    const float* __restrict__ Wk, const float* __restrict__ bk,
    const float* __restrict__ Wv, const float* __restrict__ bv)
{
    __shared__ float As[16][64];
    __shared__ float Bs[16][64];

    const int which = blockIdx.z;
    const float* W    = (which == 0) ? Wq : ((which == 1) ? Wk : Wv);
    const float* bias = (which == 0) ? bq : ((which == 1) ? bk : bv);
    float* out        = (which == 0) ? g_Q : ((which == 1) ? g_K : g_V);

    const int t  = threadIdx.x;
    const int m0 = blockIdx.y * 64;
    const int n0 = blockIdx.x * 64;
    const int lm = t & 63;        // row within tile for loading
    const int kq = t >> 6;        // which float4 along K
    const int tx = t & 15;        // micro-tile col group
    const int ty = t >> 4;        // micro-tile row group

    float acc[4][4];
#pragma unroll
    for (int i = 0; i < 4; i++)
#pragma unroll
        for (int j = 0; j < 4; j++) acc[i][j] = 0.0f;

    for (int k0 = 0; k0 < D_; k0 += 16) {
        const float4 a = *(const float4*)(x + (size_t)(m0 + lm) * D_ + k0 + kq * 4);
        const float4 w = *(const float4*)(W + (size_t)(n0 + lm) * D_ + k0 + kq * 4);
        __syncthreads();
        As[kq*4+0][lm] = a.x; As[kq*4+1][lm] = a.y;
        As[kq*4+2][lm] = a.z; As[kq*4+3][lm] = a.w;
        Bs[kq*4+0][lm] = w.x; Bs[kq*4+1][lm] = w.y;
        Bs[kq*4+2][lm] = w.z; Bs[kq*4+3][lm] = w.w;
        __syncthreads();
#pragma unroll
        for (int k = 0; k < 16; k++) {
            const float4 av = *(const float4*)&As[k][ty * 4];
            const float4 bv = *(const float4*)&Bs[k][tx * 4];
            acc[0][0] = fmaf(av.x, bv.x, acc[0][0]);
            acc[0][1] = fmaf(av.x, bv.y, acc[0][1]);
            acc[0][2] = fmaf(av.x, bv.z, acc[0][2]);
            acc[0][3] = fmaf(av.x, bv.w, acc[0][3]);
            acc[1][0] = fmaf(av.y, bv.x, acc[1][0]);
            acc[1][1] = fmaf(av.y, bv.y, acc[1][1]);
            acc[1][2] = fmaf(av.y, bv.z, acc[1][2]);
            acc[1][3] = fmaf(av.y, bv.w, acc[1][3]);
            acc[2][0] = fmaf(av.z, bv.x, acc[2][0]);
            acc[2][1] = fmaf(av.z, bv.y, acc[2][1]);
            acc[2][2] = fmaf(av.z, bv.z, acc[2][2]);
            acc[2][3] = fmaf(av.z, bv.w, acc[2][3]);
            acc[3][0] = fmaf(av.w, bv.x, acc[3][0]);
            acc[3][1] = fmaf(av.w, bv.y, acc[3][1]);
            acc[3][2] = fmaf(av.w, bv.z, acc[3][2]);
            acc[3][3] = fmaf(av.w, bv.w, acc[3][3]);
        }
    }

#pragma unroll
    for (int i = 0; i < 4; i++) {
        const int m  = m0 + ty * 4 + i;
        const int bb = m >> 12;          // m / L_
        const int l  = m & (L_ - 1);     // m % L_
#pragma unroll
        for (int j = 0; j < 4; j++) {
            const int n = n0 + tx * 4 + j;
            const int h = n >> 6;        // n / DK_
            const int d = n & 63;        // n % DK_
            out[(((size_t)(bb * H_ + h)) * L_ + l) * DK_ + d] = acc[i][j] + bias[n];
        }
    }
}

// ---------------------------------------------------------------------------
// Output projection: d_out = g_O @ Wo^T + bo, plain [M, D] output.
// ---------------------------------------------------------------------------
__global__ __launch_bounds__(256) void out_gemm(
    const float* __restrict__ Wo, const float* __restrict__ bo,
    float* __restrict__ out)
{
    __shared__ float As[16][64];
    __shared__ float Bs[16][64];

    const int t  = threadIdx.x;
    const int m0 = blockIdx.y * 64;
    const int n0 = blockIdx.x * 64;
    const int lm = t & 63;
    const int kq = t >> 6;
    const int tx = t & 15;
    const int ty = t >> 4;

    float acc[4][4];
#pragma unroll
    for (int i = 0; i < 4; i++)
#pragma unroll
        for (int j = 0; j < 4; j++) acc[i][j] = 0.0f;

    for (int k0 = 0; k0 < D_; k0 += 16) {
        const float4 a = *(const float4*)(g_O + (size_t)(m0 + lm) * D_ + k0 + kq * 4);
        const float4 w = *(const float4*)(Wo  + (size_t)(n0 + lm) * D_ + k0 + kq * 4);
        __syncthreads();
        As[kq*4+0][lm] = a.x; As[kq*4+1][lm] = a.y;
        As[kq*4+2][lm] = a.z; As[kq*4+3][lm] = a.w;
        Bs[kq*4+0][lm] = w.x; Bs[kq*4+1][lm] = w.y;
        Bs[kq*4+2][lm] = w.z; Bs[kq*4+3][lm] = w.w;
        __syncthreads();
#pragma unroll
        for (int k = 0; k < 16; k++) {
            const float4 av = *(const float4*)&As[k][ty * 4];
            const float4 bv = *(const float4*)&Bs[k][tx * 4];
            acc[0][0] = fmaf(av.x, bv.x, acc[0][0]);
            acc[0][1] = fmaf(av.x, bv.y, acc[0][1]);
            acc[0][2] = fmaf(av.x, bv.z, acc[0][2]);
            acc[0][3] = fmaf(av.x, bv.w, acc[0][3]);
            acc[1][0] = fmaf(av.y, bv.x, acc[1][0]);
            acc[1][1] = fmaf(av.y, bv.y, acc[1][1]);
            acc[1][2] = fmaf(av.y, bv.z, acc[1][2]);
            acc[1][3] = fmaf(av.y, bv.w, acc[1][3]);
            acc[2][0] = fmaf(av.z, bv.x, acc[2][0]);
            acc[2][1] = fmaf(av.z, bv.y, acc[2][1]);
            acc[2][2] = fmaf(av.z, bv.z, acc[2][2]);
            acc[2][3] = fmaf(av.z, bv.w, acc[2][3]);
            acc[3][0] = fmaf(av.w, bv.x, acc[3][0]);
            acc[3][1] = fmaf(av.w, bv.y, acc[3][1]);
            acc[3][2] = fmaf(av.w, bv.z, acc[3][2]);
            acc[3][3] = fmaf(av.w, bv.w, acc[3][3]);
        }
    }

#pragma unroll
    for (int i = 0; i < 4; i++) {
        const int m = m0 + ty * 4 + i;
#pragma unroll
        for (int j = 0; j < 4; j++) {
            const int n = n0 + tx * 4 + j;
            out[(size_t)m * D_ + n] = acc[i][j] + __ldg(bo + n);
        }
    }
}

// ---------------------------------------------------------------------------
// Flash attention (fp32, online softmax). One thread = one query row.
// Block = 128 query rows of one (b, h). K/V tiles of 32 keys in SMEM.
// Mask semantics replicate the reference exactly: masked score := -10000.
// Q is pre-scaled by 1/sqrt(dk) = 0.125.
// ---------------------------------------------------------------------------
__global__ __launch_bounds__(128, 2) void flash_attn(const int* __restrict__ mask)
{
    __shared__ float Ks[32][64];
    __shared__ float Vs[32][64];
    __shared__ int   Ms[32];

    const int t   = threadIdx.x;
    const int h   = blockIdx.y;
    const int b   = blockIdx.z;
    const int row = blockIdx.x * 128 + t;
    const size_t bh = (size_t)(b * H_ + h) * L_;

    const float4* Qp = (const float4*)(g_Q + (bh + row) * DK_);
    float4 q[16];
#pragma unroll
    for (int i = 0; i < 16; i++) {
        float4 v = Qp[i];
        v.x *= 0.125f; v.y *= 0.125f; v.z *= 0.125f; v.w *= 0.125f;
        q[i] = v;
    }
    float4 o[16];
#pragma unroll
    for (int i = 0; i < 16; i++) o[i] = make_float4(0.f, 0.f, 0.f, 0.f);

    float mrun = -3.0e38f;
    float lrun = 0.0f;
    const int* mrow = mask + b * L_;

    for (int kt = 0; kt < L_; kt += 32) {
        __syncthreads();
        const float4* Kg = (const float4*)(g_K + (bh + kt) * DK_);
        const float4* Vg = (const float4*)(g_V + (bh + kt) * DK_);
        float4* Ks4 = (float4*)&Ks[0][0];
        float4* Vs4 = (float4*)&Vs[0][0];
#pragma unroll
        for (int i = 0; i < 4; i++) {
            Ks4[t + i * 128] = Kg[t + i * 128];
            Vs4[t + i * 128] = Vg[t + i * 128];
        }
        if (t < 32) Ms[t] = mrow[kt + t];
        __syncthreads();

        float s[32];
        float tmax = -3.0e38f;
#pragma unroll
        for (int j = 0; j < 32; j++) {
            const float4* kr = (const float4*)&Ks[j][0];
            float4 acc = make_float4(0.f, 0.f, 0.f, 0.f);
#pragma unroll
            for (int d = 0; d < 16; d++) {
                const float4 kv = kr[d];
                acc.x = fmaf(q[d].x, kv.x, acc.x);
                acc.y = fmaf(q[d].y, kv.y, acc.y);
                acc.z = fmaf(q[d].z, kv.z, acc.z);
                acc.w = fmaf(q[d].w, kv.w, acc.w);
            }
            float sv = (acc.x + acc.y) + (acc.z + acc.w);
            sv = (Ms[j] == 0) ? -10000.0f : sv;
            s[j] = sv;
            tmax = fmaxf(tmax, sv);
        }

        const float mnew = fmaxf(mrun, tmax);
        const float corr = __expf(mrun - mnew);
        lrun *= corr;
#pragma unroll
        for (int i = 0; i < 16; i++) {
            o[i].x *= corr; o[i].y *= corr; o[i].z *= corr; o[i].w *= corr;
        }
#pragma unroll
        for (int j = 0; j < 32; j++) {
            const float p = __expf(s[j] - mnew);
            lrun += p;
            const float4* vr = (const float4*)&Vs[j][0];
#pragma unroll
            for (int d = 0; d < 16; d++) {
                const float4 vv = vr[d];
                o[d].x = fmaf(p, vv.x, o[d].x);
                o[d].y = fmaf(p, vv.y, o[d].y);
                o[d].z = fmaf(p, vv.z, o[d].z);
                o[d].w = fmaf(p, vv.w, o[d].w);
            }
        }
        mrun = mnew;
    }

    const float inv = 1.0f / lrun;
    float4* Op = (float4*)(g_O + ((size_t)b * L_ + row) * D_ + h * DK_);
#pragma unroll
    for (int i = 0; i < 16; i++) {
        float4 v = o[i];
        v.x *= inv; v.y *= inv; v.z *= inv; v.w *= inv;
        Op[i] = v;
    }
}

// ---------------------------------------------------------------------------
// kernel_launch: graph-capturable, allocation-free, kernel launches only.
// Input order per metadata: x, mask, Wq, bq, Wk, bk, Wv, bv, Wo, bo.
// ---------------------------------------------------------------------------
extern "C" void kernel_launch(void* const* d_in, const int* in_sizes, int n_in,
                              void* d_out, int out_size)
{
    (void)in_sizes; (void)n_in; (void)out_size;
    const float* x    = (const float*)d_in[0];
    const int*   mask = (const int*)  d_in[1];
    const float* Wq   = (const float*)d_in[2];
    const float* bq   = (const float*)d_in[3];
    const float* Wk   = (const float*)d_in[4];
    const float* bk   = (const float*)d_in[5];
    const float* Wv   = (const float*)d_in[6];
    const float* bv   = (const float*)d_in[7];
    const float* Wo   = (const float*)d_in[8];
    const float* bo   = (const float*)d_in[9];
    float* out = (float*)d_out;

    dim3 gp(D_ / 64, M_ / 64, 3);
    qkv_gemm<<<gp, 256>>>(x, Wq, bq, Wk, bk, Wv, bv);

    dim3 ga(L_ / 128, H_, B_);
    flash_attn<<<ga, 128>>>(mask);

    dim3 go(D_ / 64, M_ / 64, 1);
    out_gemm<<<go, 256>>>(Wo, bo, out);
}

// round 3
// speedup vs baseline: 1.7300x; 1.7300x over previous
#include <cuda_runtime.h>

// Problem constants
#define B_  2
#define L_  4096
#define D_  512
#define H_  8
#define DK_ 64
#define M_  (B_*L_)

// Scratch (static device globals — allocation-free per harness rules)
__device__ __align__(16) float g_Q [(size_t)B_*H_*L_*DK_];
__device__ __align__(16) float g_K [(size_t)B_*H_*L_*DK_];
__device__ __align__(16) float g_V [(size_t)B_*H_*L_*DK_];
__device__ __align__(16) float g_Kc[(size_t)B_*H_*L_*DK_];   // compacted K
__device__ __align__(16) float g_Vc[(size_t)B_*H_*L_*DK_];   // compacted V
__device__ __align__(16) float g_O [(size_t)B_*L_*D_];
__device__ int g_kidx[B_][L_];   // valid key indices per batch (ascending)
__device__ int g_nvalid[B_];     // number of valid keys per batch

// ---------------------------------------------------------------------------
// SGEMM core: 128x128 tile, BK=16, 256 threads, 8x8 micro-tile.
// Computes C = A @ W^T (+bias in epilogue). A is [M,K] row-major, W is [N,K].
// ---------------------------------------------------------------------------
#define GEMM_BODY(APTR, WPTR)                                                 \
    __shared__ float As[16][128];                                             \
    __shared__ float Bs[16][128];                                             \
    const int t  = threadIdx.x;                                               \
    const int m0 = blockIdx.y * 128;                                          \
    const int n0 = blockIdx.x * 128;                                          \
    const int tx = t & 15;                                                    \
    const int ty = t >> 4;                                                    \
    float acc[8][8];                                                          \
    _Pragma("unroll")                                                         \
    for (int i = 0; i < 8; i++)                                               \
        _Pragma("unroll")                                                     \
        for (int j = 0; j < 8; j++) acc[i][j] = 0.0f;                         \
    const int f0  = t * 2;                                                    \
    const int lr0 = f0 >> 2,       lk0 = (f0 & 3) * 4;                        \
    const int lr1 = (f0 + 1) >> 2, lk1 = ((f0 + 1) & 3) * 4;                  \
    for (int k0 = 0; k0 < D_; k0 += 16) {                                     \
        const float4 a0 = *(const float4*)(APTR + (size_t)(m0+lr0)*D_ + k0 + lk0); \
        const float4 a1 = *(const float4*)(APTR + (size_t)(m0+lr1)*D_ + k0 + lk1); \
        const float4 w0 = *(const float4*)(WPTR + (size_t)(n0+lr0)*D_ + k0 + lk0); \
        const float4 w1 = *(const float4*)(WPTR + (size_t)(n0+lr1)*D_ + k0 + lk1); \
        __syncthreads();                                                      \
        As[lk0+0][lr0]=a0.x; As[lk0+1][lr0]=a0.y; As[lk0+2][lr0]=a0.z; As[lk0+3][lr0]=a0.w; \
        As[lk1+0][lr1]=a1.x; As[lk1+1][lr1]=a1.y; As[lk1+2][lr1]=a1.z; As[lk1+3][lr1]=a1.w; \
        Bs[lk0+0][lr0]=w0.x; Bs[lk0+1][lr0]=w0.y; Bs[lk0+2][lr0]=w0.z; Bs[lk0+3][lr0]=w0.w; \
        Bs[lk1+0][lr1]=w1.x; Bs[lk1+1][lr1]=w1.y; Bs[lk1+2][lr1]=w1.z; Bs[lk1+3][lr1]=w1.w; \
        __syncthreads();                                                      \
        _Pragma("unroll")                                                     \
        for (int k = 0; k < 16; k++) {                                        \
            const float4 av0 = *(const float4*)&As[k][ty*8];                  \
            const float4 av1 = *(const float4*)&As[k][ty*8+4];                \
            const float4 bv0 = *(const float4*)&Bs[k][tx*8];                  \
            const float4 bv1 = *(const float4*)&Bs[k][tx*8+4];                \
            const float ar[8] = {av0.x,av0.y,av0.z,av0.w,av1.x,av1.y,av1.z,av1.w}; \
            const float br[8] = {bv0.x,bv0.y,bv0.z,bv0.w,bv1.x,bv1.y,bv1.z,bv1.w}; \
            _Pragma("unroll")                                                 \
            for (int i = 0; i < 8; i++)                                       \
                _Pragma("unroll")                                             \
                for (int j = 0; j < 8; j++)                                   \
                    acc[i][j] = fmaf(ar[i], br[j], acc[i][j]);                \
        }                                                                     \
    }

// QKV projection: epilogue scatters into [B,H,L,dk].
__global__ __launch_bounds__(256, 2) void qkv_gemm(
    const float* __restrict__ x,
    const float* __restrict__ Wq, const float* __restrict__ bq,
    const float* __restrict__ Wk, const float* __restrict__ bk,
    const float* __restrict__ Wv, const float* __restrict__ bv)
{
    const int which = blockIdx.z;
    const float* W    = (which == 0) ? Wq : ((which == 1) ? Wk : Wv);
    const float* bias = (which == 0) ? bq : ((which == 1) ? bk : bv);
    float* out        = (which == 0) ? g_Q : ((which == 1) ? g_K : g_V);

    GEMM_BODY(x, W)

#pragma unroll
    for (int i = 0; i < 8; i++) {
        const int m  = m0 + ty * 8 + i;
        const int bb = m >> 12;
        const int l  = m & (L_ - 1);
#pragma unroll
        for (int j = 0; j < 8; j++) {
            const int n = n0 + tx * 8 + j;
            const int h = n >> 6;
            const int d = n & 63;
            out[(((size_t)(bb * H_ + h)) * L_ + l) * DK_ + d] = acc[i][j] + __ldg(bias + n);
        }
    }
}

// Output projection: d_out = g_O @ Wo^T + bo.
__global__ __launch_bounds__(256, 2) void out_gemm(
    const float* __restrict__ Wo, const float* __restrict__ bo,
    float* __restrict__ outp)
{
    GEMM_BODY(g_O, Wo)

#pragma unroll
    for (int i = 0; i < 8; i++) {
        const int m = m0 + ty * 8 + i;
#pragma unroll
        for (int j = 0; j < 8; j++) {
            const int n = n0 + tx * 8 + j;
            outp[(size_t)m * D_ + n] = acc[i][j] + __ldg(bo + n);
        }
    }
}

// ---------------------------------------------------------------------------
// Mask compaction: per batch, stable scan of valid keys (mask != 0).
// 1024 threads, 4 elements each.
// ---------------------------------------------------------------------------
__global__ __launch_bounds__(1024) void compact_mask(const int* __restrict__ mask)
{
    __shared__ int warp_sums[32];
    const int b = blockIdx.x;
    const int t = threadIdx.x;
    const int lane = t & 31;
    const int wid  = t >> 5;
    const int* m = mask + b * L_;

    int v[4], loc[4], cnt = 0;
#pragma unroll
    for (int i = 0; i < 4; i++) {
        v[i] = (m[t * 4 + i] != 0);
        loc[i] = cnt;
        cnt += v[i];
    }
    // warp-exclusive scan of cnt
    int wp = cnt;
#pragma unroll
    for (int off = 1; off < 32; off <<= 1) {
        int n = __shfl_up_sync(0xFFFFFFFF, wp, off);
        if (lane >= off) wp += n;
    }
    wp -= cnt;  // exclusive
    if (lane == 31) warp_sums[wid] = wp + cnt;
    __syncthreads();
    if (wid == 0) {
        int s = warp_sums[lane];
        int ws = s;
#pragma unroll
        for (int off = 1; off < 32; off <<= 1) {
            int n = __shfl_up_sync(0xFFFFFFFF, ws, off);
            if (lane >= off) ws += n;
        }
        warp_sums[lane] = ws - s;  // exclusive
        if (lane == 31) g_nvalid[b] = ws;  // total (inclusive of last)
    }
    __syncthreads();
    const int base = warp_sums[wid] + wp;
#pragma unroll
    for (int i = 0; i < 4; i++)
        if (v[i]) g_kidx[b][base + loc[i]] = t * 4 + i;
}

// Gather valid K/V rows into compacted buffers. One float4 per thread per tensor.
// block 256 = 16 rows x 16 float4; grid (L_/16, H, B).
__global__ __launch_bounds__(256) void gather_kv()
{
    const int b = blockIdx.z;
    const int h = blockIdx.y;
    const int p = blockIdx.x * 16 + (threadIdx.x >> 4);  // compacted position
    const int c = threadIdx.x & 15;                       // float4 within row
    if (p >= g_nvalid[b]) return;
    const int l = g_kidx[b][p];
    const size_t bh = (size_t)(b * H_ + h) * L_;
    const float4* Ks = (const float4*)(g_K + (bh + l) * DK_);
    const float4* Vs = (const float4*)(g_V + (bh + l) * DK_);
    float4* Kd = (float4*)(g_Kc + (bh + p) * DK_);
    float4* Vd = (float4*)(g_Vc + (bh + p) * DK_);
    Kd[c] = Ks[c];
    Vd[c] = Vs[c];
}

// ---------------------------------------------------------------------------
// Flash attention over compacted (all-valid) keys. fp32, online softmax.
// One thread = one query row; 32-key K/V tiles in SMEM (broadcast reads).
// Masked keys are omitted entirely: their reference softmax weight is
// exp(-10000 - max) == 0.0f exactly in fp32.
// ---------------------------------------------------------------------------
__global__ __launch_bounds__(128, 2) void flash_attn()
{
    __shared__ float Ks[32][64];
    __shared__ float Vs[32][64];

    const int t   = threadIdx.x;
    const int h   = blockIdx.y;
    const int b   = blockIdx.z;
    const int row = blockIdx.x * 128 + t;
    const size_t bh = (size_t)(b * H_ + h) * L_;
    const int nv = g_nvalid[b];

    const float4* Qp = (const float4*)(g_Q + (bh + row) * DK_);
    float4 q[16];
#pragma unroll
    for (int i = 0; i < 16; i++) {
        float4 v = Qp[i];
        v.x *= 0.125f; v.y *= 0.125f; v.z *= 0.125f; v.w *= 0.125f;
        q[i] = v;
    }
    float4 o[16];
#pragma unroll
    for (int i = 0; i < 16; i++) o[i] = make_float4(0.f, 0.f, 0.f, 0.f);

    float mrun = -3.0e38f;
    float lrun = 0.0f;

    for (int kt = 0; kt < nv; kt += 32) {
        const int rem = nv - kt;  // >=1
        __syncthreads();
        const float4* Kg = (const float4*)(g_Kc + (bh + kt) * DK_);
        const float4* Vg = (const float4*)(g_Vc + (bh + kt) * DK_);
        float4* Ks4 = (float4*)&Ks[0][0];
        float4* Vs4 = (float4*)&Vs[0][0];
#pragma unroll
        for (int i = 0; i < 4; i++) {
            Ks4[t + i * 128] = Kg[t + i * 128];
            Vs4[t + i * 128] = Vg[t + i * 128];
        }
        __syncthreads();

        float s[32];
        float tmax = -3.0e38f;
#pragma unroll
        for (int j = 0; j < 32; j++) {
            const float4* kr = (const float4*)&Ks[j][0];
            float4 acc = make_float4(0.f, 0.f, 0.f, 0.f);
#pragma unroll
            for (int d = 0; d < 16; d++) {
                const float4 kv = kr[d];
                acc.x = fmaf(q[d].x, kv.x, acc.x);
                acc.y = fmaf(q[d].y, kv.y, acc.y);
                acc.z = fmaf(q[d].z, kv.z, acc.z);
                acc.w = fmaf(q[d].w, kv.w, acc.w);
            }
            float sv = (acc.x + acc.y) + (acc.z + acc.w);
            sv = (j < rem) ? sv : -1.0e30f;
            s[j] = sv;
            tmax = fmaxf(tmax, sv);
        }

        const float mnew = fmaxf(mrun, tmax);
        const float corr = __expf(mrun - mnew);
        lrun *= corr;
#pragma unroll
        for (int i = 0; i < 16; i++) {
            o[i].x *= corr; o[i].y *= corr; o[i].z *= corr; o[i].w *= corr;
        }
#pragma unroll
        for (int j = 0; j < 32; j++) {
            const float p = __expf(s[j] - mnew);
            lrun += p;
            const float4* vr = (const float4*)&Vs[j][0];
#pragma unroll
            for (int d = 0; d < 16; d++) {
                const float4 vv = vr[d];
                o[d].x = fmaf(p, vv.x, o[d].x);
                o[d].y = fmaf(p, vv.y, o[d].y);
                o[d].z = fmaf(p, vv.z, o[d].z);
                o[d].w = fmaf(p, vv.w, o[d].w);
            }
        }
        mrun = mnew;
    }

    const float inv = 1.0f / lrun;
    float4* Op = (float4*)(g_O + ((size_t)b * L_ + row) * D_ + h * DK_);
#pragma unroll
    for (int i = 0; i < 16; i++) {
        float4 v = o[i];
        v.x *= inv; v.y *= inv; v.z *= inv; v.w *= inv;
        Op[i] = v;
    }
}

// ---------------------------------------------------------------------------
// kernel_launch
// ---------------------------------------------------------------------------
extern "C" void kernel_launch(void* const* d_in, const int* in_sizes, int n_in,
                              void* d_out, int out_size)
{
    (void)in_sizes; (void)n_in; (void)out_size;
    const float* x    = (const float*)d_in[0];
    const int*   mask = (const int*)  d_in[1];
    const float* Wq   = (const float*)d_in[2];
    const float* bq   = (const float*)d_in[3];
    const float* Wk   = (const float*)d_in[4];
    const float* bk   = (const float*)d_in[5];
    const float* Wv   = (const float*)d_in[6];
    const float* bv   = (const float*)d_in[7];
    const float* Wo   = (const float*)d_in[8];
    const float* bo   = (const float*)d_in[9];
    float* out = (float*)d_out;

    compact_mask<<<B_, 1024>>>(mask);

    dim3 gp(D_ / 128, M_ / 128, 3);
    qkv_gemm<<<gp, 256>>>(x, Wq, bq, Wk, bk, Wv, bv);

    dim3 gg(L_ / 16, H_, B_);
    gather_kv<<<gg, 256>>>();

    dim3 ga(L_ / 128, H_, B_);
    flash_attn<<<ga, 128>>>();

    dim3 go(D_ / 128, M_ / 128, 1);
    out_gemm<<<go, 256>>>(Wo, bo, out);
}

// round 5
// speedup vs baseline: 3.4841x; 2.0140x over previous
#include <cuda_runtime.h>
#include <cuda_bf16.h>
#include <cstdint>

// Problem constants
#define B_  2
#define L_  4096
#define D_  512
#define H_  8
#define DK_ 64
#define M_  (B_*L_)

// Scratch (static device globals — allocation-free per harness rules)
__device__ __align__(16) float g_Q [(size_t)B_*H_*L_*DK_];
__device__ __align__(16) float g_K [(size_t)B_*H_*L_*DK_];
__device__ __align__(16) float g_V [(size_t)B_*H_*L_*DK_];
__device__ __align__(16) float g_Kc[(size_t)B_*H_*L_*DK_];
__device__ __align__(16) float g_Vc[(size_t)B_*H_*L_*DK_];
__device__ __align__(16) float g_O [(size_t)B_*L_*D_];
__device__ int g_kidx[B_][L_];
__device__ int g_nvalid[B_];

// ---------------------------------------------------------------------------
// SGEMM core: 128x128 tile, BK=16, 256 threads, 8x8 micro-tile.
// ---------------------------------------------------------------------------
#define GEMM_BODY(APTR, WPTR)                                                 \
    __shared__ float As[16][128];                                             \
    __shared__ float Bs[16][128];                                             \
    const int t  = threadIdx.x;                                               \
    const int m0 = blockIdx.y * 128;                                          \
    const int n0 = blockIdx.x * 128;                                          \
    const int tx = t & 15;                                                    \
    const int ty = t >> 4;                                                    \
    float acc[8][8];                                                          \
    _Pragma("unroll")                                                         \
    for (int i = 0; i < 8; i++)                                               \
        _Pragma("unroll")                                                     \
        for (int j = 0; j < 8; j++) acc[i][j] = 0.0f;                         \
    const int f0  = t * 2;                                                    \
    const int lr0 = f0 >> 2,       lk0 = (f0 & 3) * 4;                        \
    const int lr1 = (f0 + 1) >> 2, lk1 = ((f0 + 1) & 3) * 4;                  \
    for (int k0 = 0; k0 < D_; k0 += 16) {                                     \
        const float4 a0 = *(const float4*)(APTR + (size_t)(m0+lr0)*D_ + k0 + lk0); \
        const float4 a1 = *(const float4*)(APTR + (size_t)(m0+lr1)*D_ + k0 + lk1); \
        const float4 w0 = *(const float4*)(WPTR + (size_t)(n0+lr0)*D_ + k0 + lk0); \
        const float4 w1 = *(const float4*)(WPTR + (size_t)(n0+lr1)*D_ + k0 + lk1); \
        __syncthreads();                                                      \
        As[lk0+0][lr0]=a0.x; As[lk0+1][lr0]=a0.y; As[lk0+2][lr0]=a0.z; As[lk0+3][lr0]=a0.w; \
        As[lk1+0][lr1]=a1.x; As[lk1+1][lr1]=a1.y; As[lk1+2][lr1]=a1.z; As[lk1+3][lr1]=a1.w; \
        Bs[lk0+0][lr0]=w0.x; Bs[lk0+1][lr0]=w0.y; Bs[lk0+2][lr0]=w0.z; Bs[lk0+3][lr0]=w0.w; \
        Bs[lk1+0][lr1]=w1.x; Bs[lk1+1][lr1]=w1.y; Bs[lk1+2][lr1]=w1.z; Bs[lk1+3][lr1]=w1.w; \
        __syncthreads();                                                      \
        _Pragma("unroll")                                                     \
        for (int k = 0; k < 16; k++) {                                        \
            const float4 av0 = *(const float4*)&As[k][ty*8];                  \
            const float4 av1 = *(const float4*)&As[k][ty*8+4];                \
            const float4 bv0 = *(const float4*)&Bs[k][tx*8];                  \
            const float4 bv1 = *(const float4*)&Bs[k][tx*8+4];                \
            const float ar[8] = {av0.x,av0.y,av0.z,av0.w,av1.x,av1.y,av1.z,av1.w}; \
            const float br[8] = {bv0.x,bv0.y,bv0.z,bv0.w,bv1.x,bv1.y,bv1.z,bv1.w}; \
            _Pragma("unroll")                                                 \
            for (int i = 0; i < 8; i++)                                       \
                _Pragma("unroll")                                             \
                for (int j = 0; j < 8; j++)                                   \
                    acc[i][j] = fmaf(ar[i], br[j], acc[i][j]);                \
        }                                                                     \
    }

__global__ __launch_bounds__(256, 2) void qkv_gemm(
    const float* __restrict__ x,
    const float* __restrict__ Wq, const float* __restrict__ bq,
    const float* __restrict__ Wk, const float* __restrict__ bk,
    const float* __restrict__ Wv, const float* __restrict__ bv)
{
    const int which = blockIdx.z;
    const float* W    = (which == 0) ? Wq : ((which == 1) ? Wk : Wv);
    const float* bias = (which == 0) ? bq : ((which == 1) ? bk : bv);
    float* out        = (which == 0) ? g_Q : ((which == 1) ? g_K : g_V);

    GEMM_BODY(x, W)

#pragma unroll
    for (int i = 0; i < 8; i++) {
        const int m  = m0 + ty * 8 + i;
        const int bb = m >> 12;
        const int l  = m & (L_ - 1);
#pragma unroll
        for (int j = 0; j < 8; j++) {
            const int n = n0 + tx * 8 + j;
            const int h = n >> 6;
            const int d = n & 63;
            out[(((size_t)(bb * H_ + h)) * L_ + l) * DK_ + d] = acc[i][j] + __ldg(bias + n);
        }
    }
}

__global__ __launch_bounds__(256, 2) void out_gemm(
    const float* __restrict__ Wo, const float* __restrict__ bo,
    float* __restrict__ outp)
{
    GEMM_BODY(g_O, Wo)

#pragma unroll
    for (int i = 0; i < 8; i++) {
        const int m = m0 + ty * 8 + i;
#pragma unroll
        for (int j = 0; j < 8; j++) {
            const int n = n0 + tx * 8 + j;
            outp[(size_t)m * D_ + n] = acc[i][j] + __ldg(bo + n);
        }
    }
}

// ---------------------------------------------------------------------------
// Mask compaction + K/V gather
// ---------------------------------------------------------------------------
__global__ __launch_bounds__(1024) void compact_mask(const int* __restrict__ mask)
{
    __shared__ int warp_sums[32];
    const int b = blockIdx.x;
    const int t = threadIdx.x;
    const int lane = t & 31;
    const int wid  = t >> 5;
    const int* m = mask + b * L_;

    int v[4], loc[4], cnt = 0;
#pragma unroll
    for (int i = 0; i < 4; i++) {
        v[i] = (m[t * 4 + i] != 0);
        loc[i] = cnt;
        cnt += v[i];
    }
    int wp = cnt;
#pragma unroll
    for (int off = 1; off < 32; off <<= 1) {
        int n = __shfl_up_sync(0xFFFFFFFF, wp, off);
        if (lane >= off) wp += n;
    }
    wp -= cnt;
    if (lane == 31) warp_sums[wid] = wp + cnt;
    __syncthreads();
    if (wid == 0) {
        int s = warp_sums[lane];
        int ws = s;
#pragma unroll
        for (int off = 1; off < 32; off <<= 1) {
            int n = __shfl_up_sync(0xFFFFFFFF, ws, off);
            if (lane >= off) ws += n;
        }
        warp_sums[lane] = ws - s;
        if (lane == 31) g_nvalid[b] = ws;
    }
    __syncthreads();
    const int base = warp_sums[wid] + wp;
#pragma unroll
    for (int i = 0; i < 4; i++)
        if (v[i]) g_kidx[b][base + loc[i]] = t * 4 + i;
}

__global__ __launch_bounds__(256) void gather_kv()
{
    const int b = blockIdx.z;
    const int h = blockIdx.y;
    const int p = blockIdx.x * 16 + (threadIdx.x >> 4);
    const int c = threadIdx.x & 15;
    if (p >= g_nvalid[b]) return;
    const int l = g_kidx[b][p];
    const size_t bh = (size_t)(b * H_ + h) * L_;
    const float4* Ks = (const float4*)(g_K + (bh + l) * DK_);
    const float4* Vs = (const float4*)(g_V + (bh + l) * DK_);
    float4* Kd = (float4*)(g_Kc + (bh + p) * DK_);
    float4* Vd = (float4*)(g_Vc + (bh + p) * DK_);
    Kd[c] = Ks[c];
    Vd[c] = Vs[c];
}

// ---------------------------------------------------------------------------
// Tensor-core flash attention (mma.sync m16n8k16 bf16, 2-term split precision)
// ---------------------------------------------------------------------------
__device__ __forceinline__ uint32_t pack_hi2(float x0, float x1) {
    uint32_t r;
    asm("prmt.b32 %0, %1, %2, 0x7632;" : "=r"(r)
        : "r"(__float_as_uint(x0)), "r"(__float_as_uint(x1)));
    return r;
}
__device__ __forceinline__ float hi_part(float x) {
    return __uint_as_float(__float_as_uint(x) & 0xFFFF0000u);
}
__device__ __forceinline__ uint32_t pack_rn2(float x0, float x1) {
    uint32_t r;
    asm("cvt.rn.bf16x2.f32 %0, %1, %2;" : "=r"(r) : "f"(x1), "f"(x0));
    return r;
}
__device__ __forceinline__ void mma16816(float* d, const uint32_t* a,
                                         uint32_t b0, uint32_t b1) {
    asm volatile(
        "mma.sync.aligned.m16n8k16.row.col.f32.bf16.bf16.f32 "
        "{%0,%1,%2,%3},{%4,%5,%6,%7},{%8,%9},{%0,%1,%2,%3};"
        : "+f"(d[0]), "+f"(d[1]), "+f"(d[2]), "+f"(d[3])
        : "r"(a[0]), "r"(a[1]), "r"(a[2]), "r"(a[3]), "r"(b0), "r"(b1));
}
__device__ __forceinline__ void ldsm4(uint32_t& r0, uint32_t& r1, uint32_t& r2,
                                      uint32_t& r3, uint32_t addr) {
    asm volatile("ldmatrix.sync.aligned.m8n8.x4.shared.b16 {%0,%1,%2,%3}, [%4];"
                 : "=r"(r0), "=r"(r1), "=r"(r2), "=r"(r3) : "r"(addr));
}
__device__ __forceinline__ void ldsm4t(uint32_t& r0, uint32_t& r1, uint32_t& r2,
                                       uint32_t& r3, uint32_t addr) {
    asm volatile("ldmatrix.sync.aligned.m8n8.x4.trans.shared.b16 {%0,%1,%2,%3}, [%4];"
                 : "=r"(r0), "=r"(r1), "=r"(r2), "=r"(r3) : "r"(addr));
}
__device__ __forceinline__ uint32_t smem_u32(const void* p) {
    return (uint32_t)__cvta_generic_to_shared(p);
}
__device__ __forceinline__ uint32_t swz(int key, int dimbyte) {
    uint32_t off = (uint32_t)(key * 128 + dimbyte);
    return off ^ ((uint32_t)(key & 7) << 4);
}

__global__ __launch_bounds__(256) void flash_attn()
{
    __shared__ __align__(16) unsigned char sKh[64 * 128];
    __shared__ __align__(16) unsigned char sKl[64 * 128];
    __shared__ __align__(16) unsigned char sVh[64 * 128];
    __shared__ __align__(16) unsigned char sVl[64 * 128];

    const int t    = threadIdx.x;
    const int lane = t & 31;
    const int warp = t >> 5;
    const int h    = blockIdx.y;
    const int b    = blockIdx.z;
    const int rowbase = blockIdx.x * 128 + warp * 16;
    const size_t bh = (size_t)(b * H_ + h) * L_;
    const int nv = g_nvalid[b];

    const int g  = lane >> 2;
    const int tc = (lane & 3) * 2;

    uint32_t Ah[4][4], Al[4][4];
#pragma unroll
    for (int ks = 0; ks < 4; ks++) {
#pragma unroll
        for (int bhf = 0; bhf < 2; bhf++) {
#pragma unroll
            for (int rhf = 0; rhf < 2; rhf++) {
                const int row = rowbase + g + rhf * 8;
                const float2 xv = *(const float2*)(g_Q + (bh + row) * DK_ + ks * 16 + bhf * 8 + tc);
                const float x0 = xv.x * 0.125f, x1 = xv.y * 0.125f;
                const int r = rhf + 2 * bhf;
                Ah[ks][r] = pack_hi2(x0, x1);
                Al[ks][r] = pack_rn2(x0 - hi_part(x0), x1 - hi_part(x1));
            }
        }
    }

    float O[8][4];
#pragma unroll
    for (int nt = 0; nt < 8; nt++)
#pragma unroll
        for (int c = 0; c < 4; c++) O[nt][c] = 0.0f;

    float mrun0 = -3.0e38f, mrun1 = -3.0e38f;
    float lrun0 = 0.0f, lrun1 = 0.0f;

    const uint32_t bKh = smem_u32(sKh), bKl = smem_u32(sKl);
    const uint32_t bVh = smem_u32(sVh), bVl = smem_u32(sVl);

    for (int kt = 0; kt < nv; kt += 64) {
        const int rem = nv - kt;
        __syncthreads();
#pragma unroll
        for (int r = 0; r < 2; r++) {
            const int idx = t + 256 * r;
            const int key = idx >> 3;
            const int oc  = idx & 7;
            const uint32_t po = swz(key, oc * 16);
            float f[8];
            if (key < rem) {
                const float4 a = *(const float4*)(g_Kc + (bh + kt + key) * DK_ + oc * 8);
                const float4 c = *(const float4*)(g_Kc + (bh + kt + key) * DK_ + oc * 8 + 4);
                f[0]=a.x; f[1]=a.y; f[2]=a.z; f[3]=a.w; f[4]=c.x; f[5]=c.y; f[6]=c.z; f[7]=c.w;
            } else {
#pragma unroll
                for (int i = 0; i < 8; i++) f[i] = 0.0f;
            }
            uint4 Hv, Lv;
            Hv.x = pack_hi2(f[0], f[1]); Hv.y = pack_hi2(f[2], f[3]);
            Hv.z = pack_hi2(f[4], f[5]); Hv.w = pack_hi2(f[6], f[7]);
            Lv.x = pack_rn2(f[0]-hi_part(f[0]), f[1]-hi_part(f[1]));
            Lv.y = pack_rn2(f[2]-hi_part(f[2]), f[3]-hi_part(f[3]));
            Lv.z = pack_rn2(f[4]-hi_part(f[4]), f[5]-hi_part(f[5]));
            Lv.w = pack_rn2(f[6]-hi_part(f[6]), f[7]-hi_part(f[7]));
            *(uint4*)(sKh + po) = Hv;
            *(uint4*)(sKl + po) = Lv;

            if (key < rem) {
                const float4 a = *(const float4*)(g_Vc + (bh + kt + key) * DK_ + oc * 8);
                const float4 c = *(const float4*)(g_Vc + (bh + kt + key) * DK_ + oc * 8 + 4);
                f[0]=a.x; f[1]=a.y; f[2]=a.z; f[3]=a.w; f[4]=c.x; f[5]=c.y; f[6]=c.z; f[7]=c.w;
            } else {
#pragma unroll
                for (int i = 0; i < 8; i++) f[i] = 0.0f;
            }
            Hv.x = pack_hi2(f[0], f[1]); Hv.y = pack_hi2(f[2], f[3]);
            Hv.z = pack_hi2(f[4], f[5]); Hv.w = pack_hi2(f[6], f[7]);
            Lv.x = pack_rn2(f[0]-hi_part(f[0]), f[1]-hi_part(f[1]));
            Lv.y = pack_rn2(f[2]-hi_part(f[2]), f[3]-hi_part(f[3]));
            Lv.z = pack_rn2(f[4]-hi_part(f[4]), f[5]-hi_part(f[5]));
            Lv.w = pack_rn2(f[6]-hi_part(f[6]), f[7]-hi_part(f[7]));
            *(uint4*)(sVh + po) = Hv;
            *(uint4*)(sVl + po) = Lv;
        }
        __syncthreads();

        float S[8][4];
#pragma unroll
        for (int nt = 0; nt < 8; nt++)
#pragma unroll
            for (int c = 0; c < 4; c++) S[nt][c] = 0.0f;

#pragma unroll
        for (int ks = 0; ks < 4; ks++) {
#pragma unroll
            for (int u = 0; u < 4; u++) {
                const int mm = lane >> 3, ii = lane & 7;
                const int key = u * 16 + (mm >> 1) * 8 + ii;
                const int dby = (ks * 16 + (mm & 1) * 8) * 2;
                const uint32_t po = swz(key, dby);
                uint32_t h0, h1, h2, h3, l0, l1, l2, l3;
                ldsm4(h0, h1, h2, h3, bKh + po);
                ldsm4(l0, l1, l2, l3, bKl + po);
                mma16816(S[2*u],   Ah[ks], h0, h1);
                mma16816(S[2*u],   Ah[ks], l0, l1);
                mma16816(S[2*u],   Al[ks], h0, h1);
                mma16816(S[2*u+1], Ah[ks], h2, h3);
                mma16816(S[2*u+1], Ah[ks], l2, l3);
                mma16816(S[2*u+1], Al[ks], h2, h3);
            }
        }

        if (rem < 64) {
#pragma unroll
            for (int nt = 0; nt < 8; nt++) {
                const int c0 = nt * 8 + tc;
                if (c0     >= rem) { S[nt][0] = -1.0e30f; S[nt][2] = -1.0e30f; }
                if (c0 + 1 >= rem) { S[nt][1] = -1.0e30f; S[nt][3] = -1.0e30f; }
            }
        }

        float m0 = -3.0e38f, m1 = -3.0e38f;
#pragma unroll
        for (int nt = 0; nt < 8; nt++) {
            m0 = fmaxf(m0, fmaxf(S[nt][0], S[nt][1]));
            m1 = fmaxf(m1, fmaxf(S[nt][2], S[nt][3]));
        }
        m0 = fmaxf(m0, __shfl_xor_sync(0xFFFFFFFF, m0, 1));
        m0 = fmaxf(m0, __shfl_xor_sync(0xFFFFFFFF, m0, 2));
        m1 = fmaxf(m1, __shfl_xor_sync(0xFFFFFFFF, m1, 1));
        m1 = fmaxf(m1, __shfl_xor_sync(0xFFFFFFFF, m1, 2));
        const float mn0 = fmaxf(mrun0, m0), mn1 = fmaxf(mrun1, m1);
        const float corr0 = __expf(mrun0 - mn0), corr1 = __expf(mrun1 - mn1);
        lrun0 *= corr0; lrun1 *= corr1;
#pragma unroll
        for (int nt = 0; nt < 8; nt++) {
            O[nt][0] *= corr0; O[nt][1] *= corr0;
            O[nt][2] *= corr1; O[nt][3] *= corr1;
        }
#pragma unroll
        for (int nt = 0; nt < 8; nt++) {
            S[nt][0] = __expf(S[nt][0] - mn0);
            S[nt][1] = __expf(S[nt][1] - mn0);
            S[nt][2] = __expf(S[nt][2] - mn1);
            S[nt][3] = __expf(S[nt][3] - mn1);
            lrun0 += S[nt][0] + S[nt][1];
            lrun1 += S[nt][2] + S[nt][3];
        }
        mrun0 = mn0; mrun1 = mn1;

#pragma unroll
        for (int kv = 0; kv < 4; kv++) {
            uint32_t Ph[4], Pl[4];
            const float* s0 = S[2*kv];
            const float* s1 = S[2*kv+1];
            Ph[0] = pack_hi2(s0[0], s0[1]);
            Ph[1] = pack_hi2(s0[2], s0[3]);
            Ph[2] = pack_hi2(s1[0], s1[1]);
            Ph[3] = pack_hi2(s1[2], s1[3]);
            Pl[0] = pack_rn2(s0[0]-hi_part(s0[0]), s0[1]-hi_part(s0[1]));
            Pl[1] = pack_rn2(s0[2]-hi_part(s0[2]), s0[3]-hi_part(s0[3]));
            Pl[2] = pack_rn2(s1[0]-hi_part(s1[0]), s1[1]-hi_part(s1[1]));
            Pl[3] = pack_rn2(s1[2]-hi_part(s1[2]), s1[3]-hi_part(s1[3]));
#pragma unroll
            for (int dt = 0; dt < 4; dt++) {
                const int mm = lane >> 3, ii = lane & 7;
                const int key = kv * 16 + (mm & 1) * 8 + ii;
                const int dby = (dt * 16 + (mm >> 1) * 8) * 2;
                const uint32_t po = swz(key, dby);
                uint32_t h0, h1, h2, h3, l0, l1, l2, l3;
                ldsm4t(h0, h1, h2, h3, bVh + po);
                ldsm4t(l0, l1, l2, l3, bVl + po);
                mma16816(O[2*dt],   Ph, h0, h1);
                mma16816(O[2*dt],   Ph, l0, l1);
                mma16816(O[2*dt],   Pl, h0, h1);
                mma16816(O[2*dt+1], Ph, h2, h3);
                mma16816(O[2*dt+1], Ph, l2, l3);
                mma16816(O[2*dt+1], Pl, h2, h3);
            }
        }
    }

    lrun0 += __shfl_xor_sync(0xFFFFFFFF, lrun0, 1);
    lrun0 += __shfl_xor_sync(0xFFFFFFFF, lrun0, 2);
    lrun1 += __shfl_xor_sync(0xFFFFFFFF, lrun1, 1);
    lrun1 += __shfl_xor_sync(0xFFFFFFFF, lrun1, 2);
    const float inv0 = 1.0f / lrun0, inv1 = 1.0f / lrun1;
    const int row0 = rowbase + g, row1 = row0 + 8;
#pragma unroll
    for (int nt = 0; nt < 8; nt++) {
        const int col = h * DK_ + nt * 8 + tc;
        *(float2*)(g_O + ((size_t)b * L_ + row0) * D_ + col) =
            make_float2(O[nt][0] * inv0, O[nt][1] * inv0);
        *(float2*)(g_O + ((size_t)b * L_ + row1) * D_ + col) =
            make_float2(O[nt][2] * inv1, O[nt][3] * inv1);
    }
}

// ---------------------------------------------------------------------------
// kernel_launch
// ---------------------------------------------------------------------------
extern "C" void kernel_launch(void* const* d_in, const int* in_sizes, int n_in,
                              void* d_out, int out_size)
{
    (void)in_sizes; (void)n_in; (void)out_size;
    const float* x    = (const float*)d_in[0];
    const int*   mask = (const int*)  d_in[1];
    const float* Wq   = (const float*)d_in[2];
    const float* bq   = (const float*)d_in[3];
    const float* Wk   = (const float*)d_in[4];
    const float* bk   = (const float*)d_in[5];
    const float* Wv   = (const float*)d_in[6];
    const float* bv   = (const float*)d_in[7];
    const float* Wo   = (const float*)d_in[8];
    const float* bo   = (const float*)d_in[9];
    float* out = (float*)d_out;

    compact_mask<<<B_, 1024>>>(mask);

    dim3 gp(D_ / 128, M_ / 128, 3);
    qkv_gemm<<<gp, 256>>>(x, Wq, bq, Wk, bk, Wv, bv);

    dim3 gg(L_ / 16, H_, B_);
    gather_kv<<<gg, 256>>>();

    dim3 ga(L_ / 128, H_, B_);
    flash_attn<<<ga, 256>>>();

    dim3 go(D_ / 128, M_ / 128, 1);
    out_gemm<<<go, 256>>>(Wo, bo, out);
}

// round 6
// speedup vs baseline: 3.7329x; 1.0714x over previous
#include <cuda_runtime.h>
#include <cuda_bf16.h>
#include <cstdint>

// Problem constants
#define B_  2
#define L_  4096
#define D_  512
#define H_  8
#define DK_ 64
#define M_  (B_*L_)
#define NT_ (L_/64)   // max key tiles per (b,h)

// Scratch (static device globals — allocation-free per harness rules)
__device__ __align__(16) float g_Q [(size_t)B_*H_*L_*DK_];
__device__ __align__(16) float g_K [(size_t)B_*H_*L_*DK_];
__device__ __align__(16) float g_V [(size_t)B_*H_*L_*DK_];
__device__ __align__(16) float g_O [(size_t)B_*L_*D_];
// Pre-swizzled split-bf16 K/V tiles: [(b*H+h)][tile][8192B]. Zero-init → safe tails.
__device__ __align__(16) unsigned char g_Khs[(size_t)B_*H_*NT_*8192];
__device__ __align__(16) unsigned char g_Kls[(size_t)B_*H_*NT_*8192];
__device__ __align__(16) unsigned char g_Vhs[(size_t)B_*H_*NT_*8192];
__device__ __align__(16) unsigned char g_Vls[(size_t)B_*H_*NT_*8192];
__device__ int g_kidx[B_][L_];
__device__ int g_nvalid[B_];

// ---------------------------------------------------------------------------
// SGEMM core: 128x128 tile, BK=16, 256 threads, 8x8 micro-tile.
// ---------------------------------------------------------------------------
#define GEMM_BODY(APTR, WPTR)                                                 \
    __shared__ float As[16][128];                                             \
    __shared__ float Bs[16][128];                                             \
    const int t  = threadIdx.x;                                               \
    const int m0 = blockIdx.y * 128;                                          \
    const int n0 = blockIdx.x * 128;                                          \
    const int tx = t & 15;                                                    \
    const int ty = t >> 4;                                                    \
    float acc[8][8];                                                          \
    _Pragma("unroll")                                                         \
    for (int i = 0; i < 8; i++)                                               \
        _Pragma("unroll")                                                     \
        for (int j = 0; j < 8; j++) acc[i][j] = 0.0f;                         \
    const int f0  = t * 2;                                                    \
    const int lr0 = f0 >> 2,       lk0 = (f0 & 3) * 4;                        \
    const int lr1 = (f0 + 1) >> 2, lk1 = ((f0 + 1) & 3) * 4;                  \
    for (int k0 = 0; k0 < D_; k0 += 16) {                                     \
        const float4 a0 = *(const float4*)(APTR + (size_t)(m0+lr0)*D_ + k0 + lk0); \
        const float4 a1 = *(const float4*)(APTR + (size_t)(m0+lr1)*D_ + k0 + lk1); \
        const float4 w0 = *(const float4*)(WPTR + (size_t)(n0+lr0)*D_ + k0 + lk0); \
        const float4 w1 = *(const float4*)(WPTR + (size_t)(n0+lr1)*D_ + k0 + lk1); \
        __syncthreads();                                                      \
        As[lk0+0][lr0]=a0.x; As[lk0+1][lr0]=a0.y; As[lk0+2][lr0]=a0.z; As[lk0+3][lr0]=a0.w; \
        As[lk1+0][lr1]=a1.x; As[lk1+1][lr1]=a1.y; As[lk1+2][lr1]=a1.z; As[lk1+3][lr1]=a1.w; \
        Bs[lk0+0][lr0]=w0.x; Bs[lk0+1][lr0]=w0.y; Bs[lk0+2][lr0]=w0.z; Bs[lk0+3][lr0]=w0.w; \
        Bs[lk1+0][lr1]=w1.x; Bs[lk1+1][lr1]=w1.y; Bs[lk1+2][lr1]=w1.z; Bs[lk1+3][lr1]=w1.w; \
        __syncthreads();                                                      \
        _Pragma("unroll")                                                     \
        for (int k = 0; k < 16; k++) {                                        \
            const float4 av0 = *(const float4*)&As[k][ty*8];                  \
            const float4 av1 = *(const float4*)&As[k][ty*8+4];                \
            const float4 bv0 = *(const float4*)&Bs[k][tx*8];                  \
            const float4 bv1 = *(const float4*)&Bs[k][tx*8+4];                \
            const float ar[8] = {av0.x,av0.y,av0.z,av0.w,av1.x,av1.y,av1.z,av1.w}; \
            const float br[8] = {bv0.x,bv0.y,bv0.z,bv0.w,bv1.x,bv1.y,bv1.z,bv1.w}; \
            _Pragma("unroll")                                                 \
            for (int i = 0; i < 8; i++)                                       \
                _Pragma("unroll")                                             \
                for (int j = 0; j < 8; j++)                                   \
                    acc[i][j] = fmaf(ar[i], br[j], acc[i][j]);                \
        }                                                                     \
    }

__global__ __launch_bounds__(256, 2) void qkv_gemm(
    const float* __restrict__ x,
    const float* __restrict__ Wq, const float* __restrict__ bq,
    const float* __restrict__ Wk, const float* __restrict__ bk,
    const float* __restrict__ Wv, const float* __restrict__ bv)
{
    const int which = blockIdx.z;
    const float* W    = (which == 0) ? Wq : ((which == 1) ? Wk : Wv);
    const float* bias = (which == 0) ? bq : ((which == 1) ? bk : bv);
    float* out        = (which == 0) ? g_Q : ((which == 1) ? g_K : g_V);

    GEMM_BODY(x, W)

#pragma unroll
    for (int i = 0; i < 8; i++) {
        const int m  = m0 + ty * 8 + i;
        const int bb = m >> 12;
        const int l  = m & (L_ - 1);
#pragma unroll
        for (int j = 0; j < 8; j++) {
            const int n = n0 + tx * 8 + j;
            const int h = n >> 6;
            const int d = n & 63;
            out[(((size_t)(bb * H_ + h)) * L_ + l) * DK_ + d] = acc[i][j] + __ldg(bias + n);
        }
    }
}

__global__ __launch_bounds__(256, 2) void out_gemm(
    const float* __restrict__ Wo, const float* __restrict__ bo,
    float* __restrict__ outp)
{
    GEMM_BODY(g_O, Wo)

#pragma unroll
    for (int i = 0; i < 8; i++) {
        const int m = m0 + ty * 8 + i;
#pragma unroll
        for (int j = 0; j < 8; j++) {
            const int n = n0 + tx * 8 + j;
            outp[(size_t)m * D_ + n] = acc[i][j] + __ldg(bo + n);
        }
    }
}

// ---------------------------------------------------------------------------
// bf16-split helpers
// ---------------------------------------------------------------------------
__device__ __forceinline__ uint32_t pack_hi2(float x0, float x1) {
    uint32_t r;
    asm("prmt.b32 %0, %1, %2, 0x7632;" : "=r"(r)
        : "r"(__float_as_uint(x0)), "r"(__float_as_uint(x1)));
    return r;
}
__device__ __forceinline__ float hi_part(float x) {
    return __uint_as_float(__float_as_uint(x) & 0xFFFF0000u);
}
__device__ __forceinline__ uint32_t pack_rn2(float x0, float x1) {
    uint32_t r;
    asm("cvt.rn.bf16x2.f32 %0, %1, %2;" : "=r"(r) : "f"(x1), "f"(x0));
    return r;
}
__device__ __forceinline__ uint32_t swz(int key, int dimbyte) {
    uint32_t off = (uint32_t)(key * 128 + dimbyte);
    return off ^ ((uint32_t)(key & 7) << 4);
}

// ---------------------------------------------------------------------------
// Mask compaction
// ---------------------------------------------------------------------------
__global__ __launch_bounds__(1024) void compact_mask(const int* __restrict__ mask)
{
    __shared__ int warp_sums[32];
    const int b = blockIdx.x;
    const int t = threadIdx.x;
    const int lane = t & 31;
    const int wid  = t >> 5;
    const int* m = mask + b * L_;

    int v[4], loc[4], cnt = 0;
#pragma unroll
    for (int i = 0; i < 4; i++) {
        v[i] = (m[t * 4 + i] != 0);
        loc[i] = cnt;
        cnt += v[i];
    }
    int wp = cnt;
#pragma unroll
    for (int off = 1; off < 32; off <<= 1) {
        int n = __shfl_up_sync(0xFFFFFFFF, wp, off);
        if (lane >= off) wp += n;
    }
    wp -= cnt;
    if (lane == 31) warp_sums[wid] = wp + cnt;
    __syncthreads();
    if (wid == 0) {
        int s = warp_sums[lane];
        int ws = s;
#pragma unroll
        for (int off = 1; off < 32; off <<= 1) {
            int n = __shfl_up_sync(0xFFFFFFFF, ws, off);
            if (lane >= off) ws += n;
        }
        warp_sums[lane] = ws - s;
        if (lane == 31) g_nvalid[b] = ws;
    }
    __syncthreads();
    const int base = warp_sums[wid] + wp;
#pragma unroll
    for (int i = 0; i < 4; i++)
        if (v[i]) g_kidx[b][base + loc[i]] = t * 4 + i;
}

// ---------------------------------------------------------------------------
// Gather + split-convert: valid K/V rows -> pre-swizzled split-bf16 8KB tiles.
// 8 threads per key (one 16B oct each). grid (L/32, H, B), block 256.
// ---------------------------------------------------------------------------
__global__ __launch_bounds__(256) void gather_split()
{
    const int b  = blockIdx.z;
    const int h  = blockIdx.y;
    const int p  = blockIdx.x * 32 + (threadIdx.x >> 3);
    const int c8 = threadIdx.x & 7;
    if (p >= g_nvalid[b]) return;
    const int l = g_kidx[b][p];
    const size_t bh = (size_t)(b * H_ + h) * L_;
    const size_t tb = ((size_t)(b * H_ + h) * NT_ + (p >> 6)) * 8192;
    const uint32_t so = swz(p & 63, c8 * 16);

    {
        const float4 a = *(const float4*)(g_K + (bh + l) * DK_ + c8 * 8);
        const float4 c = *(const float4*)(g_K + (bh + l) * DK_ + c8 * 8 + 4);
        const float f[8] = {a.x, a.y, a.z, a.w, c.x, c.y, c.z, c.w};
        uint4 Hv, Lv;
        Hv.x = pack_hi2(f[0], f[1]); Hv.y = pack_hi2(f[2], f[3]);
        Hv.z = pack_hi2(f[4], f[5]); Hv.w = pack_hi2(f[6], f[7]);
        Lv.x = pack_rn2(f[0]-hi_part(f[0]), f[1]-hi_part(f[1]));
        Lv.y = pack_rn2(f[2]-hi_part(f[2]), f[3]-hi_part(f[3]));
        Lv.z = pack_rn2(f[4]-hi_part(f[4]), f[5]-hi_part(f[5]));
        Lv.w = pack_rn2(f[6]-hi_part(f[6]), f[7]-hi_part(f[7]));
        *(uint4*)(g_Khs + tb + so) = Hv;
        *(uint4*)(g_Kls + tb + so) = Lv;
    }
    {
        const float4 a = *(const float4*)(g_V + (bh + l) * DK_ + c8 * 8);
        const float4 c = *(const float4*)(g_V + (bh + l) * DK_ + c8 * 8 + 4);
        const float f[8] = {a.x, a.y, a.z, a.w, c.x, c.y, c.z, c.w};
        uint4 Hv, Lv;
        Hv.x = pack_hi2(f[0], f[1]); Hv.y = pack_hi2(f[2], f[3]);
        Hv.z = pack_hi2(f[4], f[5]); Hv.w = pack_hi2(f[6], f[7]);
        Lv.x = pack_rn2(f[0]-hi_part(f[0]), f[1]-hi_part(f[1]));
        Lv.y = pack_rn2(f[2]-hi_part(f[2]), f[3]-hi_part(f[3]));
        Lv.z = pack_rn2(f[4]-hi_part(f[4]), f[5]-hi_part(f[5]));
        Lv.w = pack_rn2(f[6]-hi_part(f[6]), f[7]-hi_part(f[7]));
        *(uint4*)(g_Vhs + tb + so) = Hv;
        *(uint4*)(g_Vls + tb + so) = Lv;
    }
}

// ---------------------------------------------------------------------------
// Tensor-core flash attention: cp.async double-buffered copy of pre-swizzled
// split-bf16 tiles; mma.sync m16n8k16 bf16, 3-term split precision.
// ---------------------------------------------------------------------------
__device__ __forceinline__ void mma16816(float* d, const uint32_t* a,
                                         uint32_t b0, uint32_t b1) {
    asm volatile(
        "mma.sync.aligned.m16n8k16.row.col.f32.bf16.bf16.f32 "
        "{%0,%1,%2,%3},{%4,%5,%6,%7},{%8,%9},{%0,%1,%2,%3};"
        : "+f"(d[0]), "+f"(d[1]), "+f"(d[2]), "+f"(d[3])
        : "r"(a[0]), "r"(a[1]), "r"(a[2]), "r"(a[3]), "r"(b0), "r"(b1));
}
__device__ __forceinline__ void ldsm4(uint32_t& r0, uint32_t& r1, uint32_t& r2,
                                      uint32_t& r3, uint32_t addr) {
    asm volatile("ldmatrix.sync.aligned.m8n8.x4.shared.b16 {%0,%1,%2,%3}, [%4];"
                 : "=r"(r0), "=r"(r1), "=r"(r2), "=r"(r3) : "r"(addr));
}
__device__ __forceinline__ void ldsm4t(uint32_t& r0, uint32_t& r1, uint32_t& r2,
                                       uint32_t& r3, uint32_t addr) {
    asm volatile("ldmatrix.sync.aligned.m8n8.x4.trans.shared.b16 {%0,%1,%2,%3}, [%4];"
                 : "=r"(r0), "=r"(r1), "=r"(r2), "=r"(r3) : "r"(addr));
}
__device__ __forceinline__ uint32_t smem_u32(const void* p) {
    return (uint32_t)__cvta_generic_to_shared(p);
}
__device__ __forceinline__ void cpasync16(uint32_t saddr, const void* gptr) {
    asm volatile("cp.async.cg.shared.global [%0], [%1], 16;" :: "r"(saddr), "l"(gptr));
}

__global__ __launch_bounds__(256, 2) void flash_attn()
{
    extern __shared__ unsigned char smem[];
    // layout: [Kh s0][Kh s1][Kl s0][Kl s1][Vh s0][Vh s1][Vl s0][Vl s1], 8KB each
    const int t    = threadIdx.x;
    const int lane = t & 31;
    const int warp = t >> 5;
    const int h    = blockIdx.y;
    const int b    = blockIdx.z;
    const int rowbase = blockIdx.x * 128 + warp * 16;
    const size_t bh = (size_t)(b * H_ + h) * L_;
    const int nv = g_nvalid[b];
    const int ntiles = (nv + 63) >> 6;

    const int g  = lane >> 2;
    const int tc = (lane & 3) * 2;

    const uint32_t sb = smem_u32(smem);

    // --- Q fragments (scaled by 1/8, split) ---
    uint32_t Ah[4][4], Al[4][4];
#pragma unroll
    for (int ks = 0; ks < 4; ks++) {
#pragma unroll
        for (int bhf = 0; bhf < 2; bhf++) {
#pragma unroll
            for (int rhf = 0; rhf < 2; rhf++) {
                const int row = rowbase + g + rhf * 8;
                const float2 xv = *(const float2*)(g_Q + (bh + row) * DK_ + ks * 16 + bhf * 8 + tc);
                const float x0 = xv.x * 0.125f, x1 = xv.y * 0.125f;
                const int r = rhf + 2 * bhf;
                Ah[ks][r] = pack_hi2(x0, x1);
                Al[ks][r] = pack_rn2(x0 - hi_part(x0), x1 - hi_part(x1));
            }
        }
    }

    float O[8][4];
#pragma unroll
    for (int nt = 0; nt < 8; nt++)
#pragma unroll
        for (int c = 0; c < 4; c++) O[nt][c] = 0.0f;

    float mrun0 = -3.0e38f, mrun1 = -3.0e38f;
    float lrun0 = 0.0f, lrun1 = 0.0f;

    const size_t tbase = (size_t)(b * H_ + h) * NT_ * 8192;

    // issue cp.async copies of tile i into stage st (8 x 16B per thread)
    #define ISSUE_TILE(i, st) do {                                            \
        const size_t go = tbase + (size_t)(i) * 8192;                         \
        _Pragma("unroll")                                                     \
        for (int r = 0; r < 2; r++) {                                         \
            const uint32_t off = (uint32_t)(t * 16 + r * 4096);               \
            const uint32_t sof = (uint32_t)((st) * 8192) + off;               \
            cpasync16(sb          + sof, g_Khs + go + off);                   \
            cpasync16(sb + 16384  + sof, g_Kls + go + off);                   \
            cpasync16(sb + 32768  + sof, g_Vhs + go + off);                   \
            cpasync16(sb + 49152  + sof, g_Vls + go + off);                   \
        }                                                                     \
        asm volatile("cp.async.commit_group;");                               \
    } while (0)

    int st = 0;
    ISSUE_TILE(0, 0);

    for (int i = 0; i < ntiles; i++) {
        if (i + 1 < ntiles) {
            ISSUE_TILE(i + 1, st ^ 1);
            asm volatile("cp.async.wait_group 1;");
        } else {
            asm volatile("cp.async.wait_group 0;");
        }
        __syncthreads();

        const uint32_t bKh = sb          + st * 8192;
        const uint32_t bKl = sb + 16384  + st * 8192;
        const uint32_t bVh = sb + 32768  + st * 8192;
        const uint32_t bVl = sb + 49152  + st * 8192;
        const int rem = nv - i * 64;

        // ---- S = Q K^T ----
        float S[8][4];
#pragma unroll
        for (int nt = 0; nt < 8; nt++)
#pragma unroll
            for (int c = 0; c < 4; c++) S[nt][c] = 0.0f;

#pragma unroll
        for (int ks = 0; ks < 4; ks++) {
#pragma unroll
            for (int u = 0; u < 4; u++) {
                const int mm = lane >> 3, ii = lane & 7;
                const int key = u * 16 + (mm >> 1) * 8 + ii;
                const int dby = (ks * 16 + (mm & 1) * 8) * 2;
                const uint32_t po = swz(key, dby);
                uint32_t h0, h1, h2, h3, l0, l1, l2, l3;
                ldsm4(h0, h1, h2, h3, bKh + po);
                ldsm4(l0, l1, l2, l3, bKl + po);
                mma16816(S[2*u],   Ah[ks], h0, h1);
                mma16816(S[2*u],   Ah[ks], l0, l1);
                mma16816(S[2*u],   Al[ks], h0, h1);
                mma16816(S[2*u+1], Ah[ks], h2, h3);
                mma16816(S[2*u+1], Ah[ks], l2, l3);
                mma16816(S[2*u+1], Al[ks], h2, h3);
            }
        }

        if (rem < 64) {
#pragma unroll
            for (int nt = 0; nt < 8; nt++) {
                const int c0 = nt * 8 + tc;
                if (c0     >= rem) { S[nt][0] = -1.0e30f; S[nt][2] = -1.0e30f; }
                if (c0 + 1 >= rem) { S[nt][1] = -1.0e30f; S[nt][3] = -1.0e30f; }
            }
        }

        // ---- online softmax ----
        float m0 = -3.0e38f, m1 = -3.0e38f;
#pragma unroll
        for (int nt = 0; nt < 8; nt++) {
            m0 = fmaxf(m0, fmaxf(S[nt][0], S[nt][1]));
            m1 = fmaxf(m1, fmaxf(S[nt][2], S[nt][3]));
        }
        m0 = fmaxf(m0, __shfl_xor_sync(0xFFFFFFFF, m0, 1));
        m0 = fmaxf(m0, __shfl_xor_sync(0xFFFFFFFF, m0, 2));
        m1 = fmaxf(m1, __shfl_xor_sync(0xFFFFFFFF, m1, 1));
        m1 = fmaxf(m1, __shfl_xor_sync(0xFFFFFFFF, m1, 2));
        const float mn0 = fmaxf(mrun0, m0), mn1 = fmaxf(mrun1, m1);
        const float corr0 = __expf(mrun0 - mn0), corr1 = __expf(mrun1 - mn1);
        lrun0 *= corr0; lrun1 *= corr1;
#pragma unroll
        for (int nt = 0; nt < 8; nt++) {
            O[nt][0] *= corr0; O[nt][1] *= corr0;
            O[nt][2] *= corr1; O[nt][3] *= corr1;
        }
#pragma unroll
        for (int nt = 0; nt < 8; nt++) {
            S[nt][0] = __expf(S[nt][0] - mn0);
            S[nt][1] = __expf(S[nt][1] - mn0);
            S[nt][2] = __expf(S[nt][2] - mn1);
            S[nt][3] = __expf(S[nt][3] - mn1);
            lrun0 += S[nt][0] + S[nt][1];
            lrun1 += S[nt][2] + S[nt][3];
        }
        mrun0 = mn0; mrun1 = mn1;

        // ---- O += P V ----
#pragma unroll
        for (int kv = 0; kv < 4; kv++) {
            uint32_t Ph[4], Pl[4];
            const float* s0 = S[2*kv];
            const float* s1 = S[2*kv+1];
            Ph[0] = pack_hi2(s0[0], s0[1]);
            Ph[1] = pack_hi2(s0[2], s0[3]);
            Ph[2] = pack_hi2(s1[0], s1[1]);
            Ph[3] = pack_hi2(s1[2], s1[3]);
            Pl[0] = pack_rn2(s0[0]-hi_part(s0[0]), s0[1]-hi_part(s0[1]));
            Pl[1] = pack_rn2(s0[2]-hi_part(s0[2]), s0[3]-hi_part(s0[3]));
            Pl[2] = pack_rn2(s1[0]-hi_part(s1[0]), s1[1]-hi_part(s1[1]));
            Pl[3] = pack_rn2(s1[2]-hi_part(s1[2]), s1[3]-hi_part(s1[3]));
#pragma unroll
            for (int dt = 0; dt < 4; dt++) {
                const int mm = lane >> 3, ii = lane & 7;
                const int key = kv * 16 + (mm & 1) * 8 + ii;
                const int dby = (dt * 16 + (mm >> 1) * 8) * 2;
                const uint32_t po = swz(key, dby);
                uint32_t h0, h1, h2, h3, l0, l1, l2, l3;
                ldsm4t(h0, h1, h2, h3, bVh + po);
                ldsm4t(l0, l1, l2, l3, bVl + po);
                mma16816(O[2*dt],   Ph, h0, h1);
                mma16816(O[2*dt],   Ph, l0, l1);
                mma16816(O[2*dt],   Pl, h0, h1);
                mma16816(O[2*dt+1], Ph, h2, h3);
                mma16816(O[2*dt+1], Ph, l2, l3);
                mma16816(O[2*dt+1], Pl, h2, h3);
            }
        }
        __syncthreads();
        st ^= 1;
    }

    lrun0 += __shfl_xor_sync(0xFFFFFFFF, lrun0, 1);
    lrun0 += __shfl_xor_sync(0xFFFFFFFF, lrun0, 2);
    lrun1 += __shfl_xor_sync(0xFFFFFFFF, lrun1, 1);
    lrun1 += __shfl_xor_sync(0xFFFFFFFF, lrun1, 2);
    const float inv0 = 1.0f / lrun0, inv1 = 1.0f / lrun1;
    const int row0 = rowbase + g, row1 = row0 + 8;
#pragma unroll
    for (int nt = 0; nt < 8; nt++) {
        const int col = h * DK_ + nt * 8 + tc;
        *(float2*)(g_O + ((size_t)b * L_ + row0) * D_ + col) =
            make_float2(O[nt][0] * inv0, O[nt][1] * inv0);
        *(float2*)(g_O + ((size_t)b * L_ + row1) * D_ + col) =
            make_float2(O[nt][2] * inv1, O[nt][3] * inv1);
    }
}

// ---------------------------------------------------------------------------
// kernel_launch
// ---------------------------------------------------------------------------
extern "C" void kernel_launch(void* const* d_in, const int* in_sizes, int n_in,
                              void* d_out, int out_size)
{
    (void)in_sizes; (void)n_in; (void)out_size;
    const float* x    = (const float*)d_in[0];
    const int*   mask = (const int*)  d_in[1];
    const float* Wq   = (const float*)d_in[2];
    const float* bq   = (const float*)d_in[3];
    const float* Wk   = (const float*)d_in[4];
    const float* bk   = (const float*)d_in[5];
    const float* Wv   = (const float*)d_in[6];
    const float* bv   = (const float*)d_in[7];
    const float* Wo   = (const float*)d_in[8];
    const float* bo   = (const float*)d_in[9];
    float* out = (float*)d_out;

    cudaFuncSetAttribute(flash_attn, cudaFuncAttributeMaxDynamicSharedMemorySize, 65536);

    compact_mask<<<B_, 1024>>>(mask);

    dim3 gp(D_ / 128, M_ / 128, 3);
    qkv_gemm<<<gp, 256>>>(x, Wq, bq, Wk, bk, Wv, bv);

    dim3 gg(L_ / 32, H_, B_);
    gather_split<<<gg, 256>>>();

    dim3 ga(L_ / 128, H_, B_);
    flash_attn<<<ga, 256, 65536>>>();

    dim3 go(D_ / 128, M_ / 128, 1);
    out_gemm<<<go, 256>>>(Wo, bo, out);
}